// round 3
// baseline (speedup 1.0000x reference)
#include <cuda_runtime.h>

// Z gate on wire 0 of a 13-qubit (DIM=2) state, diagonal phase multiply.
// Inputs (metadata order): x_real[N], x_imag[N], m_real[DIM], m_imag[DIM]
// Output: float[2*N] = stack(real(y), imag(y))
//
// Element j of the state (reshaped (2,)*13, wire 0 = leading axis) is scaled
// by m[j / (N/DIM)]. For N=8192, DIM=2: idx = j >> 12.
//
// Vectorized: each thread handles 4 consecutive elements (float4). Since the
// phase index only changes every N/DIM = 4096 elements (divisible by 4), one
// m-lookup per thread.

__global__ void z_phase_kernel(const float4* __restrict__ xr,
                               const float4* __restrict__ xi,
                               const float* __restrict__ mr,
                               const float* __restrict__ mi,
                               float4* __restrict__ out_r,
                               float4* __restrict__ out_i,
                               int nvec,          // N/4
                               int idx_shift)     // log2(N/DIM) - 2 (in float4 units)
{
    int t = blockIdx.x * blockDim.x + threadIdx.x;
    if (t >= nvec) return;

    int idx = t >> idx_shift;           // which diagonal entry of M
    float a = __ldg(&mr[idx]);
    float b = __ldg(&mi[idx]);

    float4 r = xr[t];
    float4 i = xi[t];

    float4 yr, yi;
    yr.x = fmaf(r.x, a, -i.x * b);
    yr.y = fmaf(r.y, a, -i.y * b);
    yr.z = fmaf(r.z, a, -i.z * b);
    yr.w = fmaf(r.w, a, -i.w * b);

    yi.x = fmaf(r.x, b, i.x * a);
    yi.y = fmaf(r.y, b, i.y * a);
    yi.z = fmaf(r.z, b, i.z * a);
    yi.w = fmaf(r.w, b, i.w * a);

    out_r[t] = yr;
    out_i[t] = yi;
}

extern "C" void kernel_launch(void* const* d_in, const int* in_sizes, int n_in,
                              void* d_out, int out_size)
{
    const float* x_real = (const float*)d_in[0];
    const float* x_imag = (const float*)d_in[1];
    const float* m_real = (const float*)d_in[2];
    const float* m_imag = (const float*)d_in[3];
    float* out = (float*)d_out;

    const int N   = in_sizes[0];        // 8192
    const int DIM = in_sizes[2];        // 2
    const int nvec = N / 4;             // 2048 float4s per plane

    // stride of wire-0 axis in elements = N/DIM; in float4 units = N/(4*DIM).
    // idx = (4*t) / (N/DIM) = t >> log2(N/(4*DIM))
    int stride_vec = N / (4 * DIM);     // 1024
    int idx_shift = 0;
    while ((1 << idx_shift) < stride_vec) idx_shift++;

    const int threads = 256;
    const int blocks = (nvec + threads - 1) / threads;   // 8

    z_phase_kernel<<<blocks, threads>>>(
        (const float4*)x_real, (const float4*)x_imag,
        m_real, m_imag,
        (float4*)out,                    // real plane: out[0 .. N)
        (float4*)(out + N),              // imag plane: out[N .. 2N)
        nvec, idx_shift);
}

// round 4
// speedup vs baseline: 1.0213x; 1.0213x over previous
#include <cuda_runtime.h>

// Z gate on wire 0 of a 13-qubit (DIM=2) state, diagonal phase multiply.
// Inputs (metadata order): x_real[N], x_imag[N], m_real[DIM], m_imag[DIM]
// Output: float[2*N] = stack(real(y), imag(y))
//
// Element j of the state (reshaped (2,)*13, wire 0 = leading axis) is scaled
// by m[j / (N/DIM)]. For N=8192, DIM=2: idx = j >> 12.
//
// Vectorized: each thread handles 4 consecutive elements (float4). Since the
// phase index only changes every N/DIM = 4096 elements (divisible by 4), one
// m-lookup per thread.

__global__ void z_phase_kernel(const float4* __restrict__ xr,
                               const float4* __restrict__ xi,
                               const float* __restrict__ mr,
                               const float* __restrict__ mi,
                               float4* __restrict__ out_r,
                               float4* __restrict__ out_i,
                               int nvec,          // N/4
                               int idx_shift)     // log2(N/DIM) - 2 (in float4 units)
{
    int t = blockIdx.x * blockDim.x + threadIdx.x;
    if (t >= nvec) return;

    int idx = t >> idx_shift;           // which diagonal entry of M
    float a = __ldg(&mr[idx]);
    float b = __ldg(&mi[idx]);

    float4 r = xr[t];
    float4 i = xi[t];

    float4 yr, yi;
    yr.x = fmaf(r.x, a, -i.x * b);
    yr.y = fmaf(r.y, a, -i.y * b);
    yr.z = fmaf(r.z, a, -i.z * b);
    yr.w = fmaf(r.w, a, -i.w * b);

    yi.x = fmaf(r.x, b, i.x * a);
    yi.y = fmaf(r.y, b, i.y * a);
    yi.z = fmaf(r.z, b, i.z * a);
    yi.w = fmaf(r.w, b, i.w * a);

    out_r[t] = yr;
    out_i[t] = yi;
}

extern "C" void kernel_launch(void* const* d_in, const int* in_sizes, int n_in,
                              void* d_out, int out_size)
{
    const float* x_real = (const float*)d_in[0];
    const float* x_imag = (const float*)d_in[1];
    const float* m_real = (const float*)d_in[2];
    const float* m_imag = (const float*)d_in[3];
    float* out = (float*)d_out;

    const int N   = in_sizes[0];        // 8192
    const int DIM = in_sizes[2];        // 2
    const int nvec = N / 4;             // 2048 float4s per plane

    // stride of wire-0 axis in elements = N/DIM; in float4 units = N/(4*DIM).
    // idx = (4*t) / (N/DIM) = t >> log2(N/(4*DIM))
    int stride_vec = N / (4 * DIM);     // 1024
    int idx_shift = 0;
    while ((1 << idx_shift) < stride_vec) idx_shift++;

    const int threads = 256;
    const int blocks = (nvec + threads - 1) / threads;   // 8

    z_phase_kernel<<<blocks, threads>>>(
        (const float4*)x_real, (const float4*)x_imag,
        m_real, m_imag,
        (float4*)out,                    // real plane: out[0 .. N)
        (float4*)(out + N),              // imag plane: out[N .. 2N)
        nvec, idx_shift);
}

// round 5
// speedup vs baseline: 1.0378x; 1.0162x over previous
#include <cuda_runtime.h>

// Z gate on wire 0 of a 13-qubit (DIM=2) state, diagonal phase multiply.
// Inputs (metadata order): x_real[N], x_imag[N], m_real[DIM], m_imag[DIM]
// Output: float[2*N] = stack(real(y), imag(y))
//
// Element j of the state (reshaped (2,)*13, wire 0 = leading axis) is scaled
// by m[j / (N/DIM)]. For N=8192, DIM=2: idx = j >> 12.
//
// Vectorized: each thread handles 4 consecutive elements (float4). Since the
// phase index only changes every N/DIM = 4096 elements (divisible by 4), one
// m-lookup per thread.

__global__ void z_phase_kernel(const float4* __restrict__ xr,
                               const float4* __restrict__ xi,
                               const float* __restrict__ mr,
                               const float* __restrict__ mi,
                               float4* __restrict__ out_r,
                               float4* __restrict__ out_i,
                               int nvec,          // N/4
                               int idx_shift)     // log2(N/DIM) - 2 (in float4 units)
{
    int t = blockIdx.x * blockDim.x + threadIdx.x;
    if (t >= nvec) return;

    int idx = t >> idx_shift;           // which diagonal entry of M
    float a = __ldg(&mr[idx]);
    float b = __ldg(&mi[idx]);

    float4 r = xr[t];
    float4 i = xi[t];

    float4 yr, yi;
    yr.x = fmaf(r.x, a, -i.x * b);
    yr.y = fmaf(r.y, a, -i.y * b);
    yr.z = fmaf(r.z, a, -i.z * b);
    yr.w = fmaf(r.w, a, -i.w * b);

    yi.x = fmaf(r.x, b, i.x * a);
    yi.y = fmaf(r.y, b, i.y * a);
    yi.z = fmaf(r.z, b, i.z * a);
    yi.w = fmaf(r.w, b, i.w * a);

    out_r[t] = yr;
    out_i[t] = yi;
}

extern "C" void kernel_launch(void* const* d_in, const int* in_sizes, int n_in,
                              void* d_out, int out_size)
{
    const float* x_real = (const float*)d_in[0];
    const float* x_imag = (const float*)d_in[1];
    const float* m_real = (const float*)d_in[2];
    const float* m_imag = (const float*)d_in[3];
    float* out = (float*)d_out;

    const int N   = in_sizes[0];        // 8192
    const int DIM = in_sizes[2];        // 2
    const int nvec = N / 4;             // 2048 float4s per plane

    // stride of wire-0 axis in elements = N/DIM; in float4 units = N/(4*DIM).
    // idx = (4*t) / (N/DIM) = t >> log2(N/(4*DIM))
    int stride_vec = N / (4 * DIM);     // 1024
    int idx_shift = 0;
    while ((1 << idx_shift) < stride_vec) idx_shift++;

    const int threads = 256;
    const int blocks = (nvec + threads - 1) / threads;   // 8

    z_phase_kernel<<<blocks, threads>>>(
        (const float4*)x_real, (const float4*)x_imag,
        m_real, m_imag,
        (float4*)out,                    // real plane: out[0 .. N)
        (float4*)(out + N),              // imag plane: out[N .. 2N)
        nvec, idx_shift);
}